// round 1
// baseline (speedup 1.0000x reference)
#include <cuda_runtime.h>
#include <math.h>

#define CHUNKS   16
#define RES_DIM  8192
#define THREADS  256
#define BLOCKS_PER_CHUNK 27   // 432 blocks total ~= one wave at 3 blocks/SM (64KB smem each)

// ---------------------------------------------------------------------------
// Kernel 0: out = proj_vars   (d_out is the global spmv accumulator, seeded
// with the additive proj term)
// ---------------------------------------------------------------------------
__global__ void init_kernel(const float* __restrict__ proj, float* __restrict__ out, int n) {
    int i = blockIdx.x * blockDim.x + threadIdx.x;
    if (i < n) out[i] = proj[i];
}

// ---------------------------------------------------------------------------
// Kernel 1: per-chunk COO SpMV with shared-memory accumulation.
// grid = (BLOCKS_PER_CHUNK, CHUNKS). Each block:
//   - copies chunk state (32KB) into smem
//   - zeroes a 32KB smem accumulator
//   - streams its slice of nnz: acc[row] += val * state_sh[col]  (smem atomics)
//   - flushes acc into out[chunk] via global atomicAdd (spread REDG)
// ---------------------------------------------------------------------------
__global__ void spmv_kernel(const float* __restrict__ vals,
                            const int*   __restrict__ rows,
                            const int*   __restrict__ cols,
                            const float* __restrict__ state,
                            float*       __restrict__ out,
                            int nse) {
    extern __shared__ float smem[];
    float* acc = smem;            // RES_DIM floats
    float* st  = smem + RES_DIM;  // RES_DIM floats

    const int c   = blockIdx.y;
    const int blk = blockIdx.x;

    const float* __restrict__ st_g = state + (size_t)c * RES_DIM;
    for (int j = threadIdx.x; j < RES_DIM; j += THREADS) {
        acc[j] = 0.0f;
        st[j]  = st_g[j];
    }
    __syncthreads();

    const int per = (nse + gridDim.x - 1) / gridDim.x;
    const int lo  = blk * per;
    const int hi  = min(lo + per, nse);

    const size_t base = (size_t)c * nse;
    const float* __restrict__ v  = vals + base;
    const int*   __restrict__ r  = rows + base;
    const int*   __restrict__ cl = cols + base;

    int i = lo + threadIdx.x;
    // unroll-4: batch 12 independent global loads before the smem work (MLP)
    for (; i + 3 * THREADS < hi; i += 4 * THREADS) {
        float v0 = v[i];               int r0 = r[i];               int c0 = cl[i];
        float v1 = v[i +     THREADS]; int r1 = r[i +     THREADS]; int c1 = cl[i +     THREADS];
        float v2 = v[i + 2 * THREADS]; int r2 = r[i + 2 * THREADS]; int c2 = cl[i + 2 * THREADS];
        float v3 = v[i + 3 * THREADS]; int r3 = r[i + 3 * THREADS]; int c3 = cl[i + 3 * THREADS];
        atomicAdd(&acc[r0], v0 * st[c0]);
        atomicAdd(&acc[r1], v1 * st[c1]);
        atomicAdd(&acc[r2], v2 * st[c2]);
        atomicAdd(&acc[r3], v3 * st[c3]);
    }
    for (; i < hi; i += THREADS) {
        atomicAdd(&acc[r[i]], v[i] * st[cl[i]]);
    }
    __syncthreads();

    float* __restrict__ o = out + (size_t)c * RES_DIM;
    for (int j = threadIdx.x; j < RES_DIM; j += THREADS) {
        atomicAdd(&o[j], acc[j]);
    }
}

// ---------------------------------------------------------------------------
// Kernel 2: elementwise Horner of the tanh(BIAS + z) Taylor series.
// z = out[i] (already = spmv + proj); out[i] = c0 + z*(c1 + z*(... c5))
// ---------------------------------------------------------------------------
__global__ void horner_kernel(float* __restrict__ out, int n,
                              float c0, float c1, float c2,
                              float c3, float c4, float c5) {
    int i = blockIdx.x * blockDim.x + threadIdx.x;
    if (i < n) {
        float z = out[i];
        float p = c5;
        p = fmaf(z, p, c4);
        p = fmaf(z, p, c3);
        p = fmaf(z, p, c2);
        p = fmaf(z, p, c1);
        p = fmaf(z, p, c0);
        out[i] = p;
    }
}

// ---------------------------------------------------------------------------
extern "C" void kernel_launch(void* const* d_in, const int* in_sizes, int n_in,
                              void* d_out, int out_size) {
    const float* proj  = (const float*)d_in[0];
    const float* state = (const float*)d_in[1];
    const float* vals  = (const float*)d_in[2];
    const int*   rows  = (const int*)  d_in[3];
    const int*   cols  = (const int*)  d_in[4];
    float*       out   = (float*)d_out;

    const int nse = in_sizes[2] / CHUNKS;
    const int n   = out_size;  // CHUNKS * RES_DIM

    // Taylor coefficients of tanh(BIAS + z) around z=0, fp32 (matches reference)
    const float t  = tanhf(1.6f);
    const float t2 = t * t, t3 = t2 * t, t4 = t2 * t2, t6 = t4 * t2;
    const float c0 = t;
    const float c1 = 1.0f - t2;
    const float c2 = t3 - t;
    const float c3 = -t4 + (4.0f / 3.0f) * t2 - 1.0f / 3.0f;
    const float c4 = (t / 3.0f) * (3.0f * t4 - 5.0f * t2 + 2.0f);
    const float c5 = -t6 + 2.0f * t4 - (17.0f / 15.0f) * t2 + 2.0f / 15.0f;

    const int smem_bytes = 2 * RES_DIM * sizeof(float);  // 64KB
    cudaFuncSetAttribute(spmv_kernel, cudaFuncAttributeMaxDynamicSharedMemorySize, smem_bytes);

    init_kernel<<<(n + THREADS - 1) / THREADS, THREADS>>>(proj, out, n);

    dim3 grid(BLOCKS_PER_CHUNK, CHUNKS);
    spmv_kernel<<<grid, THREADS, smem_bytes>>>(vals, rows, cols, state, out, nse);

    horner_kernel<<<(n + THREADS - 1) / THREADS, THREADS>>>(out, n, c0, c1, c2, c3, c4, c5);
}